// round 1
// baseline (speedup 1.0000x reference)
#include <cuda_runtime.h>

// ---------------- scratch buffers (device globals; no allocation allowed) ----------------
static __device__ float g_feat1[134217728]; // [16,128,256,256]
static __device__ float g_feat2[33554432];  // [16,128,128,128]
static __device__ float g_feat3[16777216];  // [16,256,64,64]
static __device__ float g_feat4[8388608];   // [16,128,64,64]  (tokens, NCHW)
static __device__ float g_qmap[8388608];    // [16,128,64,64]  quantized NCHW
static __device__ float g_rec1[8388608];    // [16,128,64,64]  relu(conv_rec)
static __device__ float g_rs[4194304];      // [16,64,64,64]   conv_fin(rec1) pre-resize
static __device__ float g_wspecT[8192];
static __device__ float g_we1T[147456];
static __device__ float g_we2T[294912];
static __device__ float g_wprojT[32768];
static __device__ float g_wrecT[147456];
static __device__ float g_wfinT[8192];
static __device__ float g_c2[1024];
static __device__ int   g_idx[65536];
static __device__ double g_acc[2];          // [0]=vq sum, [1]=recon sum

// ---------------- helpers ----------------
__device__ __forceinline__ double blockReduceSum(double v) {
    __shared__ double sh[8];
    int lane = threadIdx.x & 31, w = threadIdx.x >> 5;
    #pragma unroll
    for (int o = 16; o; o >>= 1) v += __shfl_down_sync(0xffffffffu, v, o);
    if (lane == 0) sh[w] = v;
    __syncthreads();
    if (w == 0) {
        v = (lane < 8) ? sh[lane] : 0.0;
        #pragma unroll
        for (int o = 4; o; o >>= 1) v += __shfl_down_sync(0xffu, v, o);
    }
    return v;  // valid in thread 0
}

__global__ void zero_acc_kernel(double* acc) { acc[0] = 0.0; acc[1] = 0.0; }

// in [R][C] -> out [C][R]
__global__ void transpose_kernel(const float* __restrict__ in, float* __restrict__ out, int R, int C) {
    int e = blockIdx.x * blockDim.x + threadIdx.x;
    if (e < R * C) { int r = e / C, c = e % C; out[c * R + r] = in[e]; }
}

__global__ void c2_kernel(const float* __restrict__ cb, float* __restrict__ c2) {
    int k = blockIdx.x * blockDim.x + threadIdx.x;
    if (k < 1024) {
        float s = 0.f;
        #pragma unroll 8
        for (int d = 0; d < 128; d++) { float v = cb[k * 128 + d]; s += v * v; }
        c2[k] = s;
    }
}

// ---------------- 1x1 conv: block = 64 px x 64 co, thread = 4 px x 4 co ----------------
__global__ __launch_bounds__(256)
void conv1x1_kernel(const float* __restrict__ in, const float* __restrict__ wT,
                    const float* __restrict__ bias, float* __restrict__ out,
                    int Cin, int Cout, int P, int nCoT)
{
    __shared__ __align__(16) float in_s[32][64];
    __shared__ float w_s[32][64];
    int b   = blockIdx.z / nCoT;
    int co0 = (blockIdx.z % nCoT) * 64;
    int p0  = blockIdx.x * 64;
    int tid = threadIdx.x;
    int pl = tid & 15, cg = tid >> 4;

    float acc[4][4];
    #pragma unroll
    for (int jj = 0; jj < 4; jj++)
        #pragma unroll
        for (int j = 0; j < 4; j++) acc[jj][j] = 0.f;

    const float* inb = in + (size_t)b * Cin * P + p0;

    for (int ci0 = 0; ci0 < Cin; ci0 += 32) {
        __syncthreads();
        #pragma unroll
        for (int e = tid; e < 2048; e += 256) {
            int ci = e >> 6, p = e & 63;
            in_s[ci][p] = inb[(size_t)(ci0 + ci) * P + p];
        }
        for (int e = tid; e < 2048; e += 256) {
            int ci = e >> 6, c = e & 63;
            w_s[ci][c] = wT[(size_t)(ci0 + ci) * Cout + co0 + c];
        }
        __syncthreads();
        #pragma unroll 4
        for (int ci = 0; ci < 32; ci++) {
            float4 iv = *(const float4*)&in_s[ci][pl * 4];
            #pragma unroll
            for (int jj = 0; jj < 4; jj++) {
                float wv = w_s[ci][cg + 16 * jj];
                acc[jj][0] += wv * iv.x;
                acc[jj][1] += wv * iv.y;
                acc[jj][2] += wv * iv.z;
                acc[jj][3] += wv * iv.w;
            }
        }
    }
    #pragma unroll
    for (int jj = 0; jj < 4; jj++) {
        int co = co0 + cg + 16 * jj;
        float bv = bias[co];
        float4 o;
        o.x = acc[jj][0] + bv; o.y = acc[jj][1] + bv;
        o.z = acc[jj][2] + bv; o.w = acc[jj][3] + bv;
        *(float4*)&out[((size_t)b * Cout + co) * P + p0 + pl * 4] = o;
    }
}

// ---------------- 3x3 conv (stride templated), relu, block = 64 px row x 128 co ----------------
template<int STRIDE>
__global__ __launch_bounds__(256)
void conv3x3_kernel(const float* __restrict__ in, const float* __restrict__ wT,
                    const float* __restrict__ bias, float* __restrict__ out,
                    int Cin, int Cout, int IH, int IW, int OH, int OW, int nCoT)
{
    const int SW = 64 * STRIDE + 4;
    const int NV = 3 * STRIDE + 3;
    __shared__ __align__(16) float in_s[4][3][64 * STRIDE + 4];
    __shared__ float w_s[4][9][128];

    int b   = blockIdx.z / nCoT;
    int co0 = (blockIdx.z % nCoT) * 128;
    int oh  = blockIdx.y;
    int ow0 = blockIdx.x * 64;
    int tid = threadIdx.x;
    int pl = tid & 15, cg = tid >> 4;

    float acc[8][4];
    #pragma unroll
    for (int jj = 0; jj < 8; jj++)
        #pragma unroll
        for (int j = 0; j < 4; j++) acc[jj][j] = 0.f;

    const float* inb = in + (size_t)b * Cin * IH * IW;
    const int xlim = 63 * STRIDE + 2;

    for (int ci0 = 0; ci0 < Cin; ci0 += 4) {
        __syncthreads();
        int tot = 4 * 3 * SW;
        for (int e = tid; e < tot; e += 256) {
            int ci = e / (3 * SW); int r = e % (3 * SW);
            int ky = r / SW; int xx = r % SW;
            int iy = oh * STRIDE + ky - 1;
            int ix = ow0 * STRIDE + xx - 1;
            float v = 0.f;
            if ((unsigned)iy < (unsigned)IH && (unsigned)ix < (unsigned)IW && xx <= xlim)
                v = inb[((size_t)(ci0 + ci) * IH + iy) * IW + ix];
            in_s[ci][ky][xx] = v;
        }
        for (int e = tid; e < 4608; e += 256) {
            int ci = e / 1152; int r = e % 1152;
            int k = r >> 7; int c = r & 127;
            w_s[ci][k][c] = wT[((size_t)(ci0 + ci) * 9 + k) * Cout + co0 + c];
        }
        __syncthreads();
        for (int ci = 0; ci < 4; ci++) {
            #pragma unroll
            for (int ky = 0; ky < 3; ky++) {
                float iv[NV];
                if (STRIDE == 2) {
                    float4 a  = *(const float4*)&in_s[ci][ky][pl * 8];
                    float4 b4 = *(const float4*)&in_s[ci][ky][pl * 8 + 4];
                    iv[0] = a.x;  iv[1] = a.y;  iv[2] = a.z;  iv[3] = a.w;
                    iv[4] = b4.x; iv[5] = b4.y; iv[6] = b4.z; iv[7] = b4.w;
                    iv[8] = in_s[ci][ky][pl * 8 + 8];
                } else {
                    float4 a = *(const float4*)&in_s[ci][ky][pl * 4];
                    iv[0] = a.x; iv[1] = a.y; iv[2] = a.z; iv[3] = a.w;
                    iv[4] = in_s[ci][ky][pl * 4 + 4];
                    iv[5] = in_s[ci][ky][pl * 4 + 5];
                }
                #pragma unroll
                for (int kx = 0; kx < 3; kx++) {
                    #pragma unroll
                    for (int jj = 0; jj < 8; jj++) {
                        float wv = w_s[ci][ky * 3 + kx][cg + 16 * jj];
                        #pragma unroll
                        for (int j = 0; j < 4; j++)
                            acc[jj][j] += wv * iv[j * STRIDE + kx];
                    }
                }
            }
        }
    }
    #pragma unroll
    for (int jj = 0; jj < 8; jj++) {
        int co = co0 + cg + 16 * jj;
        float bv = bias[co];
        float4 o;
        o.x = fmaxf(acc[jj][0] + bv, 0.f);
        o.y = fmaxf(acc[jj][1] + bv, 0.f);
        o.z = fmaxf(acc[jj][2] + bv, 0.f);
        o.w = fmaxf(acc[jj][3] + bv, 0.f);
        *(float4*)&out[(((size_t)b * Cout + co) * OH + oh) * OW + ow0 + pl * 4] = o;
    }
}

// ---------------- VQ argmin: block = 32 tokens x 1024 codes ----------------
__global__ __launch_bounds__(256)
void vq_kernel(const float* __restrict__ feat, const float* __restrict__ cb,
               const float* __restrict__ c2, int* __restrict__ idx_out,
               float* __restrict__ idxf_out)
{
    __shared__ float z_s[128][32];
    __shared__ float c_s[32][128];
    __shared__ float z2_s[32];
    __shared__ float redv[32][16];
    __shared__ int   redi[32][16];

    int nb = blockIdx.x;
    int b = nb >> 7; int p0 = (nb & 127) << 5;
    int tid = threadIdx.x;

    for (int e = tid; e < 4096; e += 256) {
        int d = e >> 5, t = e & 31;
        z_s[d][t] = feat[((size_t)b * 128 + d) * 4096 + p0 + t];
    }
    __syncthreads();
    if (tid < 32) {
        float s = 0.f;
        #pragma unroll 8
        for (int d = 0; d < 128; d++) { float v = z_s[d][tid]; s += v * v; }
        z2_s[tid] = s;
    }
    __syncthreads();

    int tl = tid & 15, cg = tid >> 4;
    const float INF = __int_as_float(0x7f800000);
    float best0 = INF, best1 = INF;
    int bi0 = 0, bi1 = 0;
    float z20 = z2_s[tl], z21 = z2_s[tl + 16];

    for (int k0 = 0; k0 < 1024; k0 += 32) {
        __syncthreads();
        for (int e = tid; e < 4096; e += 256) {
            int kk = e >> 7, d = e & 127;
            c_s[kk][d] = cb[(size_t)(k0 + kk) * 128 + d];
        }
        __syncthreads();
        float d00 = 0.f, d01 = 0.f, d10 = 0.f, d11 = 0.f;
        #pragma unroll 8
        for (int d = 0; d < 128; d++) {
            float za = z_s[d][tl], zb = z_s[d][tl + 16];
            float ca = c_s[cg][d], cc = c_s[cg + 16][d];
            d00 += za * ca; d01 += za * cc;
            d10 += zb * ca; d11 += zb * cc;
        }
        int ka = k0 + cg, kb = k0 + cg + 16;
        float c2a = __ldg(&c2[ka]), c2b = __ldg(&c2[kb]);
        float va = (z20 - 2.f * d00) + c2a;
        float vb = (z20 - 2.f * d01) + c2b;
        float vc = (z21 - 2.f * d10) + c2a;
        float vd = (z21 - 2.f * d11) + c2b;
        if (va < best0) { best0 = va; bi0 = ka; }
        if (vb < best0) { best0 = vb; bi0 = kb; }
        if (vc < best1) { best1 = vc; bi1 = ka; }
        if (vd < best1) { best1 = vd; bi1 = kb; }
    }
    redv[tl][cg] = best0;      redi[tl][cg] = bi0;
    redv[tl + 16][cg] = best1; redi[tl + 16][cg] = bi1;
    __syncthreads();
    if (tid < 32) {
        float bv = redv[tid][0]; int bi = redi[tid][0];
        for (int g = 1; g < 16; g++) {
            float v = redv[tid][g]; int i = redi[tid][g];
            if (v < bv || (v == bv && i < bi)) { bv = v; bi = i; }
        }
        int n = b * 4096 + p0 + tid;
        idx_out[n] = bi;
        idxf_out[n] = (float)bi;
    }
}

// ---------------- quantized NCHW map + vq-loss sum ----------------
__global__ __launch_bounds__(256)
void quant_map_kernel(const float* __restrict__ cb, const int* __restrict__ idx,
                      const float* __restrict__ feat, float* __restrict__ qmap,
                      double* __restrict__ acc)
{
    const size_t total = 8388608;
    size_t stride = (size_t)gridDim.x * blockDim.x;
    double s = 0.0;
    for (size_t e = (size_t)blockIdx.x * blockDim.x + threadIdx.x; e < total; e += stride) {
        int p = (int)(e & 4095);
        int c = (int)((e >> 12) & 127);
        int b = (int)(e >> 19);
        int k = idx[b * 4096 + p];
        float q = __ldg(&cb[k * 128 + c]);
        float z = feat[e];
        qmap[e] = q;
        float d = q - z;
        s += (double)d * (double)d;
    }
    double bs = blockReduceSum(s);
    if (threadIdx.x == 0) atomicAdd(&acc[0], bs);
}

// ---------------- quantized tokens [n,c] to d_out ----------------
__global__ __launch_bounds__(256)
void quant_out_kernel(const float* __restrict__ cb, const int* __restrict__ idx,
                      float* __restrict__ qout)
{
    const size_t total = 8388608;
    size_t stride = (size_t)gridDim.x * blockDim.x;
    for (size_t e = (size_t)blockIdx.x * blockDim.x + threadIdx.x; e < total; e += stride) {
        int n = (int)(e >> 7); int c = (int)(e & 127);
        qout[e] = __ldg(&cb[idx[n] * 128 + c]);
    }
}

// ---------------- bilinear x4 upsample (64->256) + recon write + recon-loss ----------------
__global__ __launch_bounds__(256)
void resize_loss_kernel(const float* __restrict__ rs, const float* __restrict__ x,
                        float* __restrict__ recon, double* __restrict__ acc)
{
    const size_t total = 67108864;
    size_t stride = (size_t)gridDim.x * blockDim.x;
    double s = 0.0;
    for (size_t e = (size_t)blockIdx.x * blockDim.x + threadIdx.x; e < total; e += stride) {
        int xq = (int)(e & 255);
        int yq = (int)((e >> 8) & 255);
        int c  = (int)((e >> 16) & 63);
        int b  = (int)(e >> 22);
        int ry = yq & 3, ky = yq >> 2;
        int rx = xq & 3, kx = xq >> 2;
        // src = k + (2r-3)/8 ; fracs {0.625,0.875,0.125,0.375}; i0 = k-1 for r<2 else k
        float fy = (ry == 0) ? 0.625f : (ry == 1) ? 0.875f : (ry == 2) ? 0.125f : 0.375f;
        float fx = (rx == 0) ? 0.625f : (rx == 1) ? 0.875f : (rx == 2) ? 0.125f : 0.375f;
        int y0 = ky + ((ry < 2) ? -1 : 0);
        int x0 = kx + ((rx < 2) ? -1 : 0);
        int y1 = min(y0 + 1, 63); y0 = max(y0, 0);
        int x1 = min(x0 + 1, 63); x0 = max(x0, 0);
        const float* base = rs + (((size_t)b * 64 + c) << 12);
        float v00 = base[y0 * 64 + x0], v01 = base[y0 * 64 + x1];
        float v10 = base[y1 * 64 + x0], v11 = base[y1 * 64 + x1];
        float r0 = (1.f - fx) * v00 + fx * v01;
        float r1 = (1.f - fx) * v10 + fx * v11;
        float val = (1.f - fy) * r0 + fy * r1;
        recon[e] = val;
        float d = val - x[e];
        s += (double)d * (double)d;
    }
    double bs = blockReduceSum(s);
    if (threadIdx.x == 0) atomicAdd(&acc[1], bs);
}

__global__ void finalize_kernel(const double* __restrict__ acc, float* __restrict__ out3)
{
    float rec = (float)(acc[1] / 67108864.0);
    float m   = (float)(acc[0] / 8388608.0);
    float vq  = m + 0.25f * m;
    out3[0] = rec + vq;   // loss
    out3[1] = rec;        // recon_loss
    out3[2] = vq;         // vq_loss
}

// ---------------- launch ----------------
extern "C" void kernel_launch(void* const* d_in, const int* in_sizes, int n_in,
                              void* d_out, int out_size)
{
    (void)in_sizes; (void)n_in; (void)out_size;
    const float* x      = (const float*)d_in[0];
    const float* w_spec = (const float*)d_in[1];
    const float* b_spec = (const float*)d_in[2];
    const float* w_e1   = (const float*)d_in[3];
    const float* b_e1   = (const float*)d_in[4];
    const float* w_e2   = (const float*)d_in[5];
    const float* b_e2   = (const float*)d_in[6];
    const float* w_proj = (const float*)d_in[7];
    const float* b_proj = (const float*)d_in[8];
    const float* cb     = (const float*)d_in[9];
    const float* w_rec  = (const float*)d_in[10];
    const float* b_rec  = (const float*)d_in[11];
    const float* w_fin  = (const float*)d_in[12];
    const float* b_fin  = (const float*)d_in[13];

    float* out       = (float*)d_out;
    float* out_recon = out;
    float* out_quant = out + 67108864;
    float* out_idx   = out_quant + 8388608;
    float* out_loss  = out_idx + 65536;

    float *feat1, *feat2, *feat3, *feat4, *qmap, *rec1, *rs;
    float *wspecT, *we1T, *we2T, *wprojT, *wrecT, *wfinT, *c2p;
    int* idxp; double* accp;
    cudaGetSymbolAddress((void**)&feat1,  g_feat1);
    cudaGetSymbolAddress((void**)&feat2,  g_feat2);
    cudaGetSymbolAddress((void**)&feat3,  g_feat3);
    cudaGetSymbolAddress((void**)&feat4,  g_feat4);
    cudaGetSymbolAddress((void**)&qmap,   g_qmap);
    cudaGetSymbolAddress((void**)&rec1,   g_rec1);
    cudaGetSymbolAddress((void**)&rs,     g_rs);
    cudaGetSymbolAddress((void**)&wspecT, g_wspecT);
    cudaGetSymbolAddress((void**)&we1T,   g_we1T);
    cudaGetSymbolAddress((void**)&we2T,   g_we2T);
    cudaGetSymbolAddress((void**)&wprojT, g_wprojT);
    cudaGetSymbolAddress((void**)&wrecT,  g_wrecT);
    cudaGetSymbolAddress((void**)&wfinT,  g_wfinT);
    cudaGetSymbolAddress((void**)&c2p,    g_c2);
    cudaGetSymbolAddress((void**)&idxp,   g_idx);
    cudaGetSymbolAddress((void**)&accp,   g_acc);

    zero_acc_kernel<<<1, 1>>>(accp);
    transpose_kernel<<<(8192 + 255) / 256, 256>>>(w_spec, wspecT, 128, 64);
    transpose_kernel<<<(147456 + 255) / 256, 256>>>(w_e1, we1T, 128, 1152);
    transpose_kernel<<<(294912 + 255) / 256, 256>>>(w_e2, we2T, 256, 1152);
    transpose_kernel<<<(32768 + 255) / 256, 256>>>(w_proj, wprojT, 128, 256);
    transpose_kernel<<<(147456 + 255) / 256, 256>>>(w_rec, wrecT, 128, 1152);
    transpose_kernel<<<(8192 + 255) / 256, 256>>>(w_fin, wfinT, 64, 128);
    c2_kernel<<<4, 256>>>(cb, c2p);

    // spec 1x1: x[16,64,256,256] -> feat1[16,128,256,256]
    conv1x1_kernel<<<dim3(1024, 1, 32), 256>>>(x, wspecT, b_spec, feat1, 64, 128, 65536, 2);
    // e1 3x3 s2 relu: feat1 -> feat2[16,128,128,128]
    conv3x3_kernel<2><<<dim3(2, 128, 16), 256>>>(feat1, we1T, b_e1, feat2, 128, 128, 256, 256, 128, 128, 1);
    // e2 3x3 s2 relu: feat2 -> feat3[16,256,64,64]
    conv3x3_kernel<2><<<dim3(1, 64, 32), 256>>>(feat2, we2T, b_e2, feat3, 128, 256, 128, 128, 64, 64, 2);
    // proj 1x1: feat3 -> feat4[16,128,64,64]
    conv1x1_kernel<<<dim3(64, 1, 32), 256>>>(feat3, wprojT, b_proj, feat4, 256, 128, 4096, 2);
    // VQ
    vq_kernel<<<2048, 256>>>(feat4, cb, c2p, idxp, out_idx);
    quant_map_kernel<<<2048, 256>>>(cb, idxp, feat4, qmap, accp);
    quant_out_kernel<<<2048, 256>>>(cb, idxp, out_quant);
    // rec 3x3 s1 relu: qmap -> rec1
    conv3x3_kernel<1><<<dim3(1, 64, 16), 256>>>(qmap, wrecT, b_rec, rec1, 128, 128, 64, 64, 64, 64, 1);
    // fin 1x1 folded BEFORE resize (1x1 conv commutes with bilinear resize): rec1 -> rs[16,64,64,64]
    conv1x1_kernel<<<dim3(64, 1, 16), 256>>>(rec1, wfinT, b_fin, rs, 128, 64, 4096, 1);
    // bilinear x4 upsample + recon write + recon_loss
    resize_loss_kernel<<<4096, 256>>>(rs, x, out_recon, accp);
    finalize_kernel<<<1, 1>>>(accp, out_loss);
}

// round 3
// speedup vs baseline: 1.3622x; 1.3622x over previous
#include <cuda_runtime.h>

// ---------------- scratch buffers (device globals; no allocation allowed) ----------------
static __device__ float g_feat2[33554432];  // [16,128,128,128]
static __device__ float g_feat3[16777216];  // [16,256,64,64]
static __device__ float g_feat4[8388608];   // [16,128,64,64]  (tokens, NCHW)
static __device__ float g_qmap[8388608];    // [16,128,64,64]  quantized NCHW
static __device__ float g_rec1[8388608];    // [16,128,64,64]  relu(conv_rec)
static __device__ float g_rs[4194304];      // [16,64,64,64]   conv_fin(rec1) pre-resize
static __device__ float g_we1T[147456];     // transposed w_e1 (for fold)
static __device__ float g_wcombT[73728];    // folded spec+e1 weights [(ci*9+k)*128+co], ci<64
static __device__ float g_btab[512];        // folded bias table [4][128]
static __device__ float g_we2T[294912];
static __device__ float g_wprojT[32768];
static __device__ float g_wrecT[147456];
static __device__ float g_wfinT[8192];
static __device__ float g_c2[1024];
static __device__ int   g_idx[65536];
static __device__ double g_acc[2];          // [0]=vq sum, [1]=recon sum

// ---------------- helpers ----------------
__device__ __forceinline__ double blockReduceSum(double v) {
    __shared__ double sh[8];
    int lane = threadIdx.x & 31, w = threadIdx.x >> 5;
    #pragma unroll
    for (int o = 16; o; o >>= 1) v += __shfl_down_sync(0xffffffffu, v, o);
    if (lane == 0) sh[w] = v;
    __syncthreads();
    if (w == 0) {
        v = (lane < 8) ? sh[lane] : 0.0;
        #pragma unroll
        for (int o = 4; o; o >>= 1) v += __shfl_down_sync(0xffu, v, o);
    }
    return v;  // valid in thread 0
}

__global__ void zero_acc_kernel(double* acc) { acc[0] = 0.0; acc[1] = 0.0; }

// in [R][C] -> out [C][R]
__global__ void transpose_kernel(const float* __restrict__ in, float* __restrict__ out, int R, int C) {
    int e = blockIdx.x * blockDim.x + threadIdx.x;
    if (e < R * C) { int r = e / C, c = e % C; out[c * R + r] = in[e]; }
}

__global__ void c2_kernel(const float* __restrict__ cb, float* __restrict__ c2) {
    int k = blockIdx.x * blockDim.x + threadIdx.x;
    if (k < 1024) {
        float s = 0.f;
        #pragma unroll 8
        for (int d = 0; d < 128; d++) { float v = cb[k * 128 + d]; s += v * v; }
        c2[k] = s;
    }
}

// fold spec (1x1, 64->128) into e1 (3x3): wcombT[(ci*9+k)*128+co] = sum_c we1T[(c*9+k)*128+co]*wspec[c*64+ci]
__global__ void fold_w_kernel(const float* __restrict__ we1T, const float* __restrict__ wspec,
                              float* __restrict__ wcombT) {
    int e = blockIdx.x * blockDim.x + threadIdx.x;
    if (e >= 64 * 9 * 128) return;
    int co = e & 127; int r = e >> 7; int k = r % 9; int ci = r / 9;
    float s = 0.f;
    #pragma unroll 4
    for (int c = 0; c < 128; c++)
        s += we1T[(c * 9 + k) * 128 + co] * wspec[c * 64 + ci];
    wcombT[(ci * 9 + k) * 128 + co] = s;
}

// border-exact folded bias: btab[t][co], t = (oh==0?0:2)+(ow==0?0:1)
__global__ void fold_b_kernel(const float* __restrict__ we1, const float* __restrict__ bspec,
                              const float* __restrict__ be1, float* __restrict__ btab) {
    int co = threadIdx.x; // 128
    float sf = 0.f, sr = 0.f, sc = 0.f, s00 = 0.f;
    for (int c = 0; c < 128; c++) {
        float bs = bspec[c];
        #pragma unroll
        for (int k = 0; k < 9; k++) {
            float w = we1[co * 1152 + c * 9 + k] * bs;
            sf += w;
            if (k < 3) sr += w;        // ky==0 row (missing when oh==0)
            if (k % 3 == 0) sc += w;   // kx==0 col (missing when ow==0)
            if (k == 0) s00 += w;
        }
    }
    float base = be1[co];
    btab[0 * 128 + co] = base + sf - sr - sc + s00;
    btab[1 * 128 + co] = base + sf - sr;
    btab[2 * 128 + co] = base + sf - sc;
    btab[3 * 128 + co] = base + sf;
}

// ---------------- 1x1 conv: block = 64 px x 64 co, thread = 4 px x 4 co ----------------
__global__ __launch_bounds__(256)
void conv1x1_kernel(const float* __restrict__ in, const float* __restrict__ wT,
                    const float* __restrict__ bias, float* __restrict__ out,
                    int Cin, int Cout, int P, int nCoT)
{
    __shared__ __align__(16) float in_s[32][64];
    __shared__ float w_s[32][64];
    int b   = blockIdx.z / nCoT;
    int co0 = (blockIdx.z % nCoT) * 64;
    int p0  = blockIdx.x * 64;
    int tid = threadIdx.x;
    int pl = tid & 15, cg = tid >> 4;

    float acc[4][4];
    #pragma unroll
    for (int jj = 0; jj < 4; jj++)
        #pragma unroll
        for (int j = 0; j < 4; j++) acc[jj][j] = 0.f;

    const float* inb = in + (size_t)b * Cin * P + p0;

    for (int ci0 = 0; ci0 < Cin; ci0 += 32) {
        __syncthreads();
        #pragma unroll
        for (int e = tid; e < 2048; e += 256) {
            int ci = e >> 6, p = e & 63;
            in_s[ci][p] = inb[(size_t)(ci0 + ci) * P + p];
        }
        for (int e = tid; e < 2048; e += 256) {
            int ci = e >> 6, c = e & 63;
            w_s[ci][c] = wT[(size_t)(ci0 + ci) * Cout + co0 + c];
        }
        __syncthreads();
        #pragma unroll 4
        for (int ci = 0; ci < 32; ci++) {
            float4 iv = *(const float4*)&in_s[ci][pl * 4];
            #pragma unroll
            for (int jj = 0; jj < 4; jj++) {
                float wv = w_s[ci][cg + 16 * jj];
                acc[jj][0] += wv * iv.x;
                acc[jj][1] += wv * iv.y;
                acc[jj][2] += wv * iv.z;
                acc[jj][3] += wv * iv.w;
            }
        }
    }
    #pragma unroll
    for (int jj = 0; jj < 4; jj++) {
        int co = co0 + cg + 16 * jj;
        float bv = bias[co];
        float4 o;
        o.x = acc[jj][0] + bv; o.y = acc[jj][1] + bv;
        o.z = acc[jj][2] + bv; o.w = acc[jj][3] + bv;
        *(float4*)&out[((size_t)b * Cout + co) * P + p0 + pl * 4] = o;
    }
}

// ---------------- 3x3 conv (stride templated), relu; block = 64 px row x 128 co ----------------
// thread = 4 px x 8 consecutive co; weights read as 2x float4
// BTAB: bias is a [4][Cout] table selected by (oh==0, ow==0) -- used by the folded spec+e1 conv
template<int STRIDE, bool BTAB>
__global__ __launch_bounds__(256)
void conv3x3_kernel(const float* __restrict__ in, const float* __restrict__ wT,
                    const float* __restrict__ bias, float* __restrict__ out,
                    int Cin, int Cout, int IH, int IW, int OH, int OW, int nCoT)
{
    const int SW = 64 * STRIDE + 4;
    const int NV = 3 * STRIDE + 3;
    __shared__ __align__(16) float in_s[4][3][64 * STRIDE + 4];
    __shared__ __align__(16) float w_s[4][9][128];

    int b   = blockIdx.z / nCoT;
    int co0 = (blockIdx.z % nCoT) * 128;
    int oh  = blockIdx.y;
    int ow0 = blockIdx.x * 64;
    int tid = threadIdx.x;
    int pl = tid & 15, cg = tid >> 4;

    float acc[8][4];
    #pragma unroll
    for (int jj = 0; jj < 8; jj++)
        #pragma unroll
        for (int j = 0; j < 4; j++) acc[jj][j] = 0.f;

    const float* inb = in + (size_t)b * Cin * IH * IW;
    const int xlim = 63 * STRIDE + 2;

    for (int ci0 = 0; ci0 < Cin; ci0 += 4) {
        __syncthreads();
        int tot = 4 * 3 * SW;
        for (int e = tid; e < tot; e += 256) {
            int ci = e / (3 * SW); int r = e % (3 * SW);
            int ky = r / SW; int xx = r % SW;
            int iy = oh * STRIDE + ky - 1;
            int ix = ow0 * STRIDE + xx - 1;
            float v = 0.f;
            if ((unsigned)iy < (unsigned)IH && (unsigned)ix < (unsigned)IW && xx <= xlim)
                v = inb[((size_t)(ci0 + ci) * IH + iy) * IW + ix];
            in_s[ci][ky][xx] = v;
        }
        for (int e = tid; e < 4608; e += 256) {
            int ci = e / 1152; int r = e % 1152;
            int k = r >> 7; int c = r & 127;
            w_s[ci][k][c] = wT[((size_t)(ci0 + ci) * 9 + k) * Cout + co0 + c];
        }
        __syncthreads();
        for (int ci = 0; ci < 4; ci++) {
            #pragma unroll
            for (int ky = 0; ky < 3; ky++) {
                float iv[NV];
                if (STRIDE == 2) {
                    float4 a  = *(const float4*)&in_s[ci][ky][pl * 8];
                    float4 b4 = *(const float4*)&in_s[ci][ky][pl * 8 + 4];
                    iv[0] = a.x;  iv[1] = a.y;  iv[2] = a.z;  iv[3] = a.w;
                    iv[4] = b4.x; iv[5] = b4.y; iv[6] = b4.z; iv[7] = b4.w;
                    iv[8] = in_s[ci][ky][pl * 8 + 8];
                } else {
                    float4 a = *(const float4*)&in_s[ci][ky][pl * 4];
                    iv[0] = a.x; iv[1] = a.y; iv[2] = a.z; iv[3] = a.w;
                    iv[4] = in_s[ci][ky][pl * 4 + 4];
                    iv[5] = in_s[ci][ky][pl * 4 + 5];
                }
                #pragma unroll
                for (int kx = 0; kx < 3; kx++) {
                    float4 wa = *(const float4*)&w_s[ci][ky * 3 + kx][cg * 8];
                    float4 wb = *(const float4*)&w_s[ci][ky * 3 + kx][cg * 8 + 4];
                    float wv[8] = {wa.x, wa.y, wa.z, wa.w, wb.x, wb.y, wb.z, wb.w};
                    #pragma unroll
                    for (int jj = 0; jj < 8; jj++)
                        #pragma unroll
                        for (int j = 0; j < 4; j++)
                            acc[jj][j] += wv[jj] * iv[j * STRIDE + kx];
                }
            }
        }
    }
    #pragma unroll
    for (int jj = 0; jj < 8; jj++) {
        int co = co0 + cg * 8 + jj;
        float4 o;
        if (BTAB) {
            int rbase = (oh == 0) ? 0 : 2;
            float ov[4];
            #pragma unroll
            for (int j = 0; j < 4; j++) {
                int ow = ow0 + pl * 4 + j;
                float bv = bias[(rbase + (ow == 0 ? 0 : 1)) * Cout + co];
                ov[j] = fmaxf(acc[jj][j] + bv, 0.f);
            }
            o.x = ov[0]; o.y = ov[1]; o.z = ov[2]; o.w = ov[3];
        } else {
            float bv = bias[co];
            o.x = fmaxf(acc[jj][0] + bv, 0.f);
            o.y = fmaxf(acc[jj][1] + bv, 0.f);
            o.z = fmaxf(acc[jj][2] + bv, 0.f);
            o.w = fmaxf(acc[jj][3] + bv, 0.f);
        }
        *(float4*)&out[(((size_t)b * Cout + co) * OH + oh) * OW + ow0 + pl * 4] = o;
    }
}

// ---------------- VQ argmin + fused quantized writes + vq-loss: block = 32 tokens ----------------
__global__ __launch_bounds__(256)
void vq_kernel(const float* __restrict__ feat, const float* __restrict__ cb,
               const float* __restrict__ c2, int* __restrict__ idx_out,
               float* __restrict__ idxf_out, float* __restrict__ qmap,
               float* __restrict__ qout, double* __restrict__ acc)
{
    __shared__ float z_s[128][32];
    __shared__ float c_s[32][128];
    __shared__ float z2_s[32];
    __shared__ float redv[32][16];
    __shared__ int   redi[32][16];
    __shared__ int   bsel[32];

    int nb = blockIdx.x;
    int b = nb >> 7; int p0 = (nb & 127) << 5;
    int tid = threadIdx.x;

    for (int e = tid; e < 4096; e += 256) {
        int d = e >> 5, t = e & 31;
        z_s[d][t] = feat[((size_t)b * 128 + d) * 4096 + p0 + t];
    }
    __syncthreads();
    if (tid < 32) {
        float s = 0.f;
        #pragma unroll 8
        for (int d = 0; d < 128; d++) { float v = z_s[d][tid]; s += v * v; }
        z2_s[tid] = s;
    }
    __syncthreads();

    int tl = tid & 15, cg = tid >> 4;
    const float INF = __int_as_float(0x7f800000);
    float best0 = INF, best1 = INF;
    int bi0 = 0, bi1 = 0;
    float z20 = z2_s[tl], z21 = z2_s[tl + 16];

    for (int k0 = 0; k0 < 1024; k0 += 32) {
        __syncthreads();
        for (int e = tid; e < 4096; e += 256) {
            int kk = e >> 7, d = e & 127;
            c_s[kk][d] = cb[(size_t)(k0 + kk) * 128 + d];
        }
        __syncthreads();
        float d00 = 0.f, d01 = 0.f, d10 = 0.f, d11 = 0.f;
        #pragma unroll 8
        for (int d = 0; d < 128; d++) {
            float za = z_s[d][tl], zb = z_s[d][tl + 16];
            float ca = c_s[cg][d], cc = c_s[cg + 16][d];
            d00 += za * ca; d01 += za * cc;
            d10 += zb * ca; d11 += zb * cc;
        }
        int ka = k0 + cg, kb = k0 + cg + 16;
        float c2a = __ldg(&c2[ka]), c2b = __ldg(&c2[kb]);
        float va = (z20 - 2.f * d00) + c2a;
        float vb = (z20 - 2.f * d01) + c2b;
        float vc = (z21 - 2.f * d10) + c2a;
        float vd = (z21 - 2.f * d11) + c2b;
        if (va < best0) { best0 = va; bi0 = ka; }
        if (vb < best0) { best0 = vb; bi0 = kb; }
        if (vc < best1) { best1 = vc; bi1 = ka; }
        if (vd < best1) { best1 = vd; bi1 = kb; }
    }
    redv[tl][cg] = best0;      redi[tl][cg] = bi0;
    redv[tl + 16][cg] = best1; redi[tl + 16][cg] = bi1;
    __syncthreads();
    if (tid < 32) {
        float bv = redv[tid][0]; int bi = redi[tid][0];
        for (int g = 1; g < 16; g++) {
            float v = redv[tid][g]; int i = redi[tid][g];
            if (v < bv || (v == bv && i < bi)) { bv = v; bi = i; }
        }
        int n = b * 4096 + p0 + tid;
        idx_out[n] = bi;
        idxf_out[n] = (float)bi;
        bsel[tid] = bi;
    }
    __syncthreads();

    // fused epilogue: quantized tokens [N,128] (c-fast, coalesced)
    for (int e = tid; e < 4096; e += 256) {
        int c = e & 127, t = e >> 7;
        qout[((size_t)(b * 4096 + p0 + t)) * 128 + c] = __ldg(&cb[bsel[t] * 128 + c]);
    }
    // fused epilogue: quantized NCHW map (t-fast, coalesced) + vq-loss sum
    double vs = 0.0;
    for (int e = tid; e < 4096; e += 256) {
        int t = e & 31, c = e >> 5;
        float q = __ldg(&cb[bsel[t] * 128 + c]);
        float z = z_s[c][t];
        qmap[((size_t)b * 128 + c) * 4096 + p0 + t] = q;
        float d = q - z;
        vs += (double)d * (double)d;
    }
    double bs2 = blockReduceSum(vs);
    if (tid == 0) atomicAdd(&acc[0], bs2);
}

// ---------------- bilinear x4 upsample (64->256) + recon write + recon-loss ----------------
__global__ __launch_bounds__(256)
void resize_loss_kernel(const float* __restrict__ rs, const float* __restrict__ x,
                        float* __restrict__ recon, double* __restrict__ acc)
{
    const size_t total = 67108864;
    size_t stride = (size_t)gridDim.x * blockDim.x;
    double s = 0.0;
    for (size_t e = (size_t)blockIdx.x * blockDim.x + threadIdx.x; e < total; e += stride) {
        int xq = (int)(e & 255);
        int yq = (int)((e >> 8) & 255);
        int c  = (int)((e >> 16) & 63);
        int b  = (int)(e >> 22);
        int ry = yq & 3, ky = yq >> 2;
        int rx = xq & 3, kx = xq >> 2;
        float fy = (ry == 0) ? 0.625f : (ry == 1) ? 0.875f : (ry == 2) ? 0.125f : 0.375f;
        float fx = (rx == 0) ? 0.625f : (rx == 1) ? 0.875f : (rx == 2) ? 0.125f : 0.375f;
        int y0 = ky + ((ry < 2) ? -1 : 0);
        int x0 = kx + ((rx < 2) ? -1 : 0);
        int y1 = min(y0 + 1, 63); y0 = max(y0, 0);
        int x1 = min(x0 + 1, 63); x0 = max(x0, 0);
        const float* base = rs + (((size_t)b * 64 + c) << 12);
        float v00 = base[y0 * 64 + x0], v01 = base[y0 * 64 + x1];
        float v10 = base[y1 * 64 + x0], v11 = base[y1 * 64 + x1];
        float r0 = (1.f - fx) * v00 + fx * v01;
        float r1 = (1.f - fx) * v10 + fx * v11;
        float val = (1.f - fy) * r0 + fy * r1;
        recon[e] = val;
        float d = val - x[e];
        s += (double)d * (double)d;
    }
    double bs = blockReduceSum(s);
    if (threadIdx.x == 0) atomicAdd(&acc[1], bs);
}

__global__ void finalize_kernel(const double* __restrict__ acc, float* __restrict__ out3)
{
    float rec = (float)(acc[1] / 67108864.0);
    float m   = (float)(acc[0] / 8388608.0);
    float vq  = m + 0.25f * m;
    out3[0] = rec + vq;   // loss
    out3[1] = rec;        // recon_loss
    out3[2] = vq;         // vq_loss
}

// ---------------- launch ----------------
extern "C" void kernel_launch(void* const* d_in, const int* in_sizes, int n_in,
                              void* d_out, int out_size)
{
    (void)in_sizes; (void)n_in; (void)out_size;
    const float* x      = (const float*)d_in[0];
    const float* w_spec = (const float*)d_in[1];
    const float* b_spec = (const float*)d_in[2];
    const float* w_e1   = (const float*)d_in[3];
    const float* b_e1   = (const float*)d_in[4];
    const float* w_e2   = (const float*)d_in[5];
    const float* b_e2   = (const float*)d_in[6];
    const float* w_proj = (const float*)d_in[7];
    const float* b_proj = (const float*)d_in[8];
    const float* cb     = (const float*)d_in[9];
    const float* w_rec  = (const float*)d_in[10];
    const float* b_rec  = (const float*)d_in[11];
    const float* w_fin  = (const float*)d_in[12];
    const float* b_fin  = (const float*)d_in[13];

    float* out       = (float*)d_out;
    float* out_recon = out;
    float* out_quant = out + 67108864;
    float* out_idx   = out_quant + 8388608;
    float* out_loss  = out_idx + 65536;

    float *feat2, *feat3, *feat4, *qmap, *rec1, *rs;
    float *we1T, *wcombT, *btab, *we2T, *wprojT, *wrecT, *wfinT, *c2p;
    int* idxp; double* accp;
    cudaGetSymbolAddress((void**)&feat2,  g_feat2);
    cudaGetSymbolAddress((void**)&feat3,  g_feat3);
    cudaGetSymbolAddress((void**)&feat4,  g_feat4);
    cudaGetSymbolAddress((void**)&qmap,   g_qmap);
    cudaGetSymbolAddress((void**)&rec1,   g_rec1);
    cudaGetSymbolAddress((void**)&rs,     g_rs);
    cudaGetSymbolAddress((void**)&we1T,   g_we1T);
    cudaGetSymbolAddress((void**)&wcombT, g_wcombT);
    cudaGetSymbolAddress((void**)&btab,   g_btab);
    cudaGetSymbolAddress((void**)&we2T,   g_we2T);
    cudaGetSymbolAddress((void**)&wprojT, g_wprojT);
    cudaGetSymbolAddress((void**)&wrecT,  g_wrecT);
    cudaGetSymbolAddress((void**)&wfinT,  g_wfinT);
    cudaGetSymbolAddress((void**)&c2p,    g_c2);
    cudaGetSymbolAddress((void**)&idxp,   g_idx);
    cudaGetSymbolAddress((void**)&accp,   g_acc);

    zero_acc_kernel<<<1, 1>>>(accp);
    transpose_kernel<<<(147456 + 255) / 256, 256>>>(w_e1, we1T, 128, 1152);
    fold_w_kernel<<<(73728 + 255) / 256, 256>>>(we1T, w_spec, wcombT);
    fold_b_kernel<<<1, 128>>>(w_e1, b_spec, b_e1, btab);
    transpose_kernel<<<(294912 + 255) / 256, 256>>>(w_e2, we2T, 256, 1152);
    transpose_kernel<<<(32768 + 255) / 256, 256>>>(w_proj, wprojT, 128, 256);
    transpose_kernel<<<(147456 + 255) / 256, 256>>>(w_rec, wrecT, 128, 1152);
    transpose_kernel<<<(8192 + 255) / 256, 256>>>(w_fin, wfinT, 64, 128);
    c2_kernel<<<4, 256>>>(cb, c2p);

    // folded spec+e1 3x3 s2 relu: x[16,64,256,256] -> feat2[16,128,128,128]
    conv3x3_kernel<2, true><<<dim3(2, 128, 16), 256>>>(x, wcombT, btab, feat2, 64, 128, 256, 256, 128, 128, 1);
    // e2 3x3 s2 relu: feat2 -> feat3[16,256,64,64]
    conv3x3_kernel<2, false><<<dim3(1, 64, 32), 256>>>(feat2, we2T, b_e2, feat3, 128, 256, 128, 128, 64, 64, 2);
    // proj 1x1: feat3 -> feat4[16,128,64,64]
    conv1x1_kernel<<<dim3(64, 1, 32), 256>>>(feat3, wprojT, b_proj, feat4, 256, 128, 4096, 2);
    // VQ (fused: argmin + quant tokens + quant NCHW map + vq loss)
    vq_kernel<<<2048, 256>>>(feat4, cb, c2p, idxp, out_idx, qmap, out_quant, accp);
    // rec 3x3 s1 relu: qmap -> rec1
    conv3x3_kernel<1, false><<<dim3(1, 64, 16), 256>>>(qmap, wrecT, b_rec, rec1, 128, 128, 64, 64, 64, 64, 1);
    // fin 1x1 folded BEFORE resize (1x1 conv commutes with bilinear resize): rec1 -> rs[16,64,64,64]
    conv1x1_kernel<<<dim3(64, 1, 16), 256>>>(rec1, wfinT, b_fin, rs, 128, 64, 4096, 1);
    // bilinear x4 upsample + recon write + recon_loss
    resize_loss_kernel<<<4096, 256>>>(rs, x, out_recon, accp);
    finalize_kernel<<<1, 1>>>(accp, out_loss);
}

// round 6
// speedup vs baseline: 1.5321x; 1.1247x over previous
#include <cuda_runtime.h>

// ---------------- scratch buffers (device globals; no allocation allowed) ----------------
static __device__ float g_feat2[33554432];  // [16,128,128,128]
static __device__ float g_feat3[16777216];  // [16,256,64,64]
static __device__ float g_feat4[8388608];   // [16,128,64,64]  (tokens, NCHW)
static __device__ float g_qmap[8388608];    // [16,128,64,64]  quantized NCHW
static __device__ float g_rec1[8388608];    // [16,128,64,64]  relu(conv_rec)
static __device__ float g_rs[4194304];      // [16,64,64,64]   conv_fin(rec1) pre-resize
static __device__ float g_we1T[147456];     // transposed w_e1 (for fold)
static __device__ float g_wcombT[73728];    // folded spec+e1 weights [(ci*9+k)*128+co], ci<64
static __device__ float g_btab[512];        // folded bias table [4][128]
static __device__ float g_we2T[294912];
static __device__ float g_wprojT[32768];
static __device__ float g_wrecT[147456];
static __device__ float g_wfinT[8192];
static __device__ float g_c2[1024];
static __device__ int   g_idx[65536];
static __device__ double g_acc[2];          // [0]=vq sum, [1]=recon sum

typedef unsigned long long u64;

// ---------------- packed f32x2 helpers (sm_103a; ptxas never emits FFMA2 from C++) ----------------
__device__ __forceinline__ u64 pack2(float lo, float hi) {
    u64 r; asm("mov.b64 %0, {%1, %2};" : "=l"(r) : "f"(lo), "f"(hi)); return r;
}
__device__ __forceinline__ float2 unpack2(u64 v) {
    float lo, hi; asm("mov.b64 {%0, %1}, %2;" : "=f"(lo), "=f"(hi) : "l"(v));
    return make_float2(lo, hi);
}
__device__ __forceinline__ void ffma2(u64& d, u64 a, u64 b) {
    asm("fma.rn.f32x2 %0, %1, %2, %0;" : "+l"(d) : "l"(a), "l"(b));
}

// ---------------- helpers ----------------
__device__ __forceinline__ double blockReduceSum(double v) {
    __shared__ double sh[8];
    int lane = threadIdx.x & 31, w = threadIdx.x >> 5;
    #pragma unroll
    for (int o = 16; o; o >>= 1) v += __shfl_down_sync(0xffffffffu, v, o);
    if (lane == 0) sh[w] = v;
    __syncthreads();
    if (w == 0) {
        v = (lane < 8) ? sh[lane] : 0.0;
        #pragma unroll
        for (int o = 4; o; o >>= 1) v += __shfl_down_sync(0xffu, v, o);
    }
    return v;  // valid in thread 0
}

__global__ void zero_acc_kernel(double* acc) { acc[0] = 0.0; acc[1] = 0.0; }

// in [R][C] -> out [C][R]
__global__ void transpose_kernel(const float* __restrict__ in, float* __restrict__ out, int R, int C) {
    int e = blockIdx.x * blockDim.x + threadIdx.x;
    if (e < R * C) { int r = e / C, c = e % C; out[c * R + r] = in[e]; }
}

__global__ void c2_kernel(const float* __restrict__ cb, float* __restrict__ c2) {
    int k = blockIdx.x * blockDim.x + threadIdx.x;
    if (k < 1024) {
        float s = 0.f;
        #pragma unroll 8
        for (int d = 0; d < 128; d++) { float v = cb[k * 128 + d]; s += v * v; }
        c2[k] = s;
    }
}

// fold spec (1x1, 64->128) into e1 (3x3): wcombT[(ci*9+k)*128+co] = sum_c we1T[(c*9+k)*128+co]*wspec[c*64+ci]
__global__ void fold_w_kernel(const float* __restrict__ we1T, const float* __restrict__ wspec,
                              float* __restrict__ wcombT) {
    int e = blockIdx.x * blockDim.x + threadIdx.x;
    if (e >= 64 * 9 * 128) return;
    int co = e & 127; int r = e >> 7; int k = r % 9; int ci = r / 9;
    float s = 0.f;
    #pragma unroll 4
    for (int c = 0; c < 128; c++)
        s += we1T[(c * 9 + k) * 128 + co] * wspec[c * 64 + ci];
    wcombT[(ci * 9 + k) * 128 + co] = s;
}

// border-exact folded bias: btab[t][co], t = (oh==0?0:2)+(ow==0?0:1)
// parallel: one block per co, threads over c, tree-reduce
__global__ void fold_b_kernel(const float* __restrict__ we1, const float* __restrict__ bspec,
                              const float* __restrict__ be1, float* __restrict__ btab) {
    __shared__ float red[4][128];
    int co = blockIdx.x, c = threadIdx.x;
    float bs = bspec[c];
    float w[9];
    #pragma unroll
    for (int k = 0; k < 9; k++) w[k] = we1[co * 1152 + c * 9 + k] * bs;
    float sf = 0.f;
    #pragma unroll
    for (int k = 0; k < 9; k++) sf += w[k];
    red[0][c] = sf;
    red[1][c] = w[0] + w[1] + w[2];   // ky==0 row (missing when oh==0)
    red[2][c] = w[0] + w[3] + w[6];   // kx==0 col (missing when ow==0)
    red[3][c] = w[0];
    __syncthreads();
    for (int o = 64; o; o >>= 1) {
        if (c < o) {
            #pragma unroll
            for (int q = 0; q < 4; q++) red[q][c] += red[q][c + o];
        }
        __syncthreads();
    }
    if (c == 0) {
        float base = be1[co];
        float tf = red[0][0], tr = red[1][0], tc = red[2][0], t00 = red[3][0];
        btab[0 * 128 + co] = base + tf - tr - tc + t00;
        btab[1 * 128 + co] = base + tf - tr;
        btab[2 * 128 + co] = base + tf - tc;
        btab[3 * 128 + co] = base + tf;
    }
}

// ---------------- 1x1 conv: block = 64 px x 64 co, thread = 4 px x 4 consecutive co ----------------
// packed f32x2 over the co dimension: weight pairs come straight from LDS.128
__global__ __launch_bounds__(256)
void conv1x1_kernel(const float* __restrict__ in, const float* __restrict__ wT,
                    const float* __restrict__ bias, float* __restrict__ out,
                    int Cin, int Cout, int P, int nCoT)
{
    __shared__ __align__(16) float in_s[32][64];
    __shared__ __align__(16) float w_s[32][64];
    int b   = blockIdx.z / nCoT;
    int co0 = (blockIdx.z % nCoT) * 64;
    int p0  = blockIdx.x * 64;
    int tid = threadIdx.x;
    int pl = tid & 15, cg = tid >> 4;   // pl: pixel group (4 px), cg: 4 consecutive co

    u64 accp[2][4];                      // [co pair][pixel]
    #pragma unroll
    for (int p = 0; p < 2; p++)
        #pragma unroll
        for (int j = 0; j < 4; j++) accp[p][j] = 0ULL;

    const float* inb = in + (size_t)b * Cin * P + p0;

    for (int ci0 = 0; ci0 < Cin; ci0 += 32) {
        __syncthreads();
        #pragma unroll
        for (int e = tid; e < 2048; e += 256) {
            int ci = e >> 6, p = e & 63;
            in_s[ci][p] = inb[(size_t)(ci0 + ci) * P + p];
        }
        for (int e = tid; e < 2048; e += 256) {
            int ci = e >> 6, c = e & 63;
            w_s[ci][c] = wT[(size_t)(ci0 + ci) * Cout + co0 + c];
        }
        __syncthreads();
        #pragma unroll 4
        for (int ci = 0; ci < 32; ci++) {
            float4 iv = *(const float4*)&in_s[ci][pl * 4];
            u64 ivb[4] = {pack2(iv.x, iv.x), pack2(iv.y, iv.y),
                          pack2(iv.z, iv.z), pack2(iv.w, iv.w)};
            ulonglong2 w2 = *(const ulonglong2*)&w_s[ci][cg * 4];
            #pragma unroll
            for (int j = 0; j < 4; j++) { ffma2(accp[0][j], w2.x, ivb[j]); }
            #pragma unroll
            for (int j = 0; j < 4; j++) { ffma2(accp[1][j], w2.y, ivb[j]); }
        }
    }
    #pragma unroll
    for (int p = 0; p < 2; p++) {
        int coA = co0 + cg * 4 + p * 2;
        float bA = bias[coA], bB = bias[coA + 1];
        float2 v0 = unpack2(accp[p][0]), v1 = unpack2(accp[p][1]);
        float2 v2 = unpack2(accp[p][2]), v3 = unpack2(accp[p][3]);
        float4 oA, oB;
        oA.x = v0.x + bA; oA.y = v1.x + bA; oA.z = v2.x + bA; oA.w = v3.x + bA;
        oB.x = v0.y + bB; oB.y = v1.y + bB; oB.z = v2.y + bB; oB.w = v3.y + bB;
        *(float4*)&out[((size_t)b * Cout + coA)     * P + p0 + pl * 4] = oA;
        *(float4*)&out[((size_t)b * Cout + coA + 1) * P + p0 + pl * 4] = oB;
    }
}

// ---------------- 3x3 conv (stride templated), relu; block = 64 px row x 128 co ----------------
// thread = 4 px x 8 consecutive co; f32x2 packed over co (4 co-pairs), weight pairs direct from LDS.128
// BTAB: bias is a [4][Cout] table selected by (oh==0, ow==0) -- used by the folded spec+e1 conv
template<int STRIDE, bool BTAB>
__global__ __launch_bounds__(256)
void conv3x3_kernel(const float* __restrict__ in, const float* __restrict__ wT,
                    const float* __restrict__ bias, float* __restrict__ out,
                    int Cin, int Cout, int IH, int IW, int OH, int OW, int nCoT)
{
    const int SW = 64 * STRIDE + 4;
    const int NV = 3 * STRIDE + 3;
    __shared__ __align__(16) float in_s[4][3][64 * STRIDE + 4];
    __shared__ __align__(16) float w_s[4][9][128];

    int b   = blockIdx.z / nCoT;
    int co0 = (blockIdx.z % nCoT) * 128;
    int oh  = blockIdx.y;
    int ow0 = blockIdx.x * 64;
    int tid = threadIdx.x;
    int pl = tid & 15, cg = tid >> 4;

    u64 accp[4][4];                      // [co pair][pixel]
    #pragma unroll
    for (int q = 0; q < 4; q++)
        #pragma unroll
        for (int j = 0; j < 4; j++) accp[q][j] = 0ULL;

    const float* inb = in + (size_t)b * Cin * IH * IW;
    const int xlim = 63 * STRIDE + 2;

    for (int ci0 = 0; ci0 < Cin; ci0 += 4) {
        __syncthreads();
        int tot = 4 * 3 * SW;
        for (int e = tid; e < tot; e += 256) {
            int ci = e / (3 * SW); int r = e % (3 * SW);
            int ky = r / SW; int xx = r % SW;
            int iy = oh * STRIDE + ky - 1;
            int ix = ow0 * STRIDE + xx - 1;
            float v = 0.f;
            if ((unsigned)iy < (unsigned)IH && (unsigned)ix < (unsigned)IW && xx <= xlim)
                v = inb[((size_t)(ci0 + ci) * IH + iy) * IW + ix];
            in_s[ci][ky][xx] = v;
        }
        for (int e = tid; e < 4608; e += 256) {
            int ci = e / 1152; int r = e % 1152;
            int k = r >> 7; int c = r & 127;
            w_s[ci][k][c] = wT[((size_t)(ci0 + ci) * 9 + k) * Cout + co0 + c];
        }
        __syncthreads();
        for (int ci = 0; ci < 4; ci++) {
            #pragma unroll
            for (int ky = 0; ky < 3; ky++) {
                float iv[NV];
                if (STRIDE == 2) {
                    float4 a  = *(const float4*)&in_s[ci][ky][pl * 8];
                    float4 b4 = *(const float4*)&in_s[ci][ky][pl * 8 + 4];
                    iv[0] = a.x;  iv[1] = a.y;  iv[2] = a.z;  iv[3] = a.w;
                    iv[4] = b4.x; iv[5] = b4.y; iv[6] = b4.z; iv[7] = b4.w;
                    iv[8] = in_s[ci][ky][pl * 8 + 8];
                } else {
                    float4 a = *(const float4*)&in_s[ci][ky][pl * 4];
                    iv[0] = a.x; iv[1] = a.y; iv[2] = a.z; iv[3] = a.w;
                    iv[4] = in_s[ci][ky][pl * 4 + 4];
                    iv[5] = in_s[ci][ky][pl * 4 + 5];
                }
                u64 ivb[NV];
                #pragma unroll
                for (int v = 0; v < NV; v++) ivb[v] = pack2(iv[v], iv[v]);
                #pragma unroll
                for (int kx = 0; kx < 3; kx++) {
                    const ulonglong2* wrow = (const ulonglong2*)&w_s[ci][ky * 3 + kx][cg * 8];
                    ulonglong2 wA = wrow[0], wB = wrow[1];
                    u64 wq[4] = {wA.x, wA.y, wB.x, wB.y};
                    #pragma unroll
                    for (int q = 0; q < 4; q++)
                        #pragma unroll
                        for (int j = 0; j < 4; j++)
                            ffma2(accp[q][j], wq[q], ivb[j * STRIDE + kx]);
                }
            }
        }
    }
    #pragma unroll
    for (int q = 0; q < 4; q++) {
        int coA = co0 + cg * 8 + q * 2;
        int coB = coA + 1;
        float2 v0 = unpack2(accp[q][0]), v1 = unpack2(accp[q][1]);
        float2 v2 = unpack2(accp[q][2]), v3 = unpack2(accp[q][3]);
        float4 oA, oB;
        if (BTAB) {
            int rbase = (oh == 0) ? 0 : 2;
            float pa[4] = {v0.x, v1.x, v2.x, v3.x};
            float pb[4] = {v0.y, v1.y, v2.y, v3.y};
            float ra[4], rb[4];
            #pragma unroll
            for (int j = 0; j < 4; j++) {
                int ow = ow0 + pl * 4 + j;
                int t = rbase + (ow == 0 ? 0 : 1);
                ra[j] = fmaxf(pa[j] + bias[t * Cout + coA], 0.f);
                rb[j] = fmaxf(pb[j] + bias[t * Cout + coB], 0.f);
            }
            oA.x = ra[0]; oA.y = ra[1]; oA.z = ra[2]; oA.w = ra[3];
            oB.x = rb[0]; oB.y = rb[1]; oB.z = rb[2]; oB.w = rb[3];
        } else {
            float bA = bias[coA], bB = bias[coB];
            oA.x = fmaxf(v0.x + bA, 0.f); oA.y = fmaxf(v1.x + bA, 0.f);
            oA.z = fmaxf(v2.x + bA, 0.f); oA.w = fmaxf(v3.x + bA, 0.f);
            oB.x = fmaxf(v0.y + bB, 0.f); oB.y = fmaxf(v1.y + bB, 0.f);
            oB.z = fmaxf(v2.y + bB, 0.f); oB.w = fmaxf(v3.y + bB, 0.f);
        }
        *(float4*)&out[(((size_t)b * Cout + coA) * OH + oh) * OW + ow0 + pl * 4] = oA;
        *(float4*)&out[(((size_t)b * Cout + coB) * OH + oh) * OW + ow0 + pl * 4] = oB;
    }
}

// ---------------- VQ argmin + fused quantized writes + vq-loss: block = 32 tokens ----------------
__global__ __launch_bounds__(256)
void vq_kernel(const float* __restrict__ feat, const float* __restrict__ cb,
               const float* __restrict__ c2, int* __restrict__ idx_out,
               float* __restrict__ idxf_out, float* __restrict__ qmap,
               float* __restrict__ qout, double* __restrict__ acc)
{
    __shared__ float z_s[128][32];
    __shared__ float c_s[32][128];
    __shared__ float z2_s[32];
    __shared__ float redv[32][16];
    __shared__ int   redi[32][16];
    __shared__ int   bsel[32];

    int nb = blockIdx.x;
    int b = nb >> 7; int p0 = (nb & 127) << 5;
    int tid = threadIdx.x;

    for (int e = tid; e < 4096; e += 256) {
        int d = e >> 5, t = e & 31;
        z_s[d][t] = feat[((size_t)b * 128 + d) * 4096 + p0 + t];
    }
    __syncthreads();
    if (tid < 32) {
        float s = 0.f;
        #pragma unroll 8
        for (int d = 0; d < 128; d++) { float v = z_s[d][tid]; s += v * v; }
        z2_s[tid] = s;
    }
    __syncthreads();

    int tl = tid & 15, cg = tid >> 4;
    const float INF = __int_as_float(0x7f800000);
    float best0 = INF, best1 = INF;
    int bi0 = 0, bi1 = 0;
    float z20 = z2_s[tl], z21 = z2_s[tl + 16];

    for (int k0 = 0; k0 < 1024; k0 += 32) {
        __syncthreads();
        for (int e = tid; e < 4096; e += 256) {
            int kk = e >> 7, d = e & 127;
            c_s[kk][d] = cb[(size_t)(k0 + kk) * 128 + d];
        }
        __syncthreads();
        float d00 = 0.f, d01 = 0.f, d10 = 0.f, d11 = 0.f;
        #pragma unroll 8
        for (int d = 0; d < 128; d++) {
            float za = z_s[d][tl], zb = z_s[d][tl + 16];
            float ca = c_s[cg][d], cc = c_s[cg + 16][d];
            d00 += za * ca; d01 += za * cc;
            d10 += zb * ca; d11 += zb * cc;
        }
        int ka = k0 + cg, kb = k0 + cg + 16;
        float c2a = __ldg(&c2[ka]), c2b = __ldg(&c2[kb]);
        float va = (z20 - 2.f * d00) + c2a;
        float vb = (z20 - 2.f * d01) + c2b;
        float vc = (z21 - 2.f * d10) + c2a;
        float vd = (z21 - 2.f * d11) + c2b;
        if (va < best0) { best0 = va; bi0 = ka; }
        if (vb < best0) { best0 = vb; bi0 = kb; }
        if (vc < best1) { best1 = vc; bi1 = ka; }
        if (vd < best1) { best1 = vd; bi1 = kb; }
    }
    redv[tl][cg] = best0;      redi[tl][cg] = bi0;
    redv[tl + 16][cg] = best1; redi[tl + 16][cg] = bi1;
    __syncthreads();
    if (tid < 32) {
        float bv = redv[tid][0]; int bi = redi[tid][0];
        for (int g = 1; g < 16; g++) {
            float v = redv[tid][g]; int i = redi[tid][g];
            if (v < bv || (v == bv && i < bi)) { bv = v; bi = i; }
        }
        int n = b * 4096 + p0 + tid;
        idx_out[n] = bi;
        idxf_out[n] = (float)bi;
        bsel[tid] = bi;
    }
    __syncthreads();

    // fused epilogue: quantized tokens [N,128] (c-fast, coalesced)
    for (int e = tid; e < 4096; e += 256) {
        int c = e & 127, t = e >> 7;
        qout[((size_t)(b * 4096 + p0 + t)) * 128 + c] = __ldg(&cb[bsel[t] * 128 + c]);
    }
    // fused epilogue: quantized NCHW map (t-fast, coalesced) + vq-loss sum
    double vs = 0.0;
    for (int e = tid; e < 4096; e += 256) {
        int t = e & 31, c = e >> 5;
        float q = __ldg(&cb[bsel[t] * 128 + c]);
        float z = z_s[c][t];
        qmap[((size_t)b * 128 + c) * 4096 + p0 + t] = q;
        float d = q - z;
        vs += (double)d * (double)d;
    }
    double bs2 = blockReduceSum(vs);
    if (tid == 0) atomicAdd(&acc[0], bs2);
}

// ---------------- bilinear x4 upsample (64->256) + recon write + recon-loss ----------------
__global__ __launch_bounds__(256)
void resize_loss_kernel(const float* __restrict__ rs, const float* __restrict__ x,
                        float* __restrict__ recon, double* __restrict__ acc)
{
    const size_t total = 67108864;
    size_t stride = (size_t)gridDim.x * blockDim.x;
    double s = 0.0;
    for (size_t e = (size_t)blockIdx.x * blockDim.x + threadIdx.x; e < total; e += stride) {
        int xq = (int)(e & 255);
        int yq = (int)((e >> 8) & 255);
        int c  = (int)((e >> 16) & 63);
        int b  = (int)(e >> 22);
        int ry = yq & 3, ky = yq >> 2;
        int rx = xq & 3, kx = xq >> 2;
        float fy = (ry == 0) ? 0.625f : (ry == 1) ? 0.875f : (ry == 2) ? 0.125f : 0.375f;
        float fx = (rx == 0) ? 0.625f : (rx == 1) ? 0.875f : (rx == 2) ? 0.125f : 0.375f;
        int y0 = ky + ((ry < 2) ? -1 : 0);
        int x0 = kx + ((rx < 2) ? -1 : 0);
        int y1 = min(y0 + 1, 63); y0 = max(y0, 0);
        int x1 = min(x0 + 1, 63); x0 = max(x0, 0);
        const float* base = rs + (((size_t)b * 64 + c) << 12);
        float v00 = base[y0 * 64 + x0], v01 = base[y0 * 64 + x1];
        float v10 = base[y1 * 64 + x0], v11 = base[y1 * 64 + x1];
        float r0 = (1.f - fx) * v00 + fx * v01;
        float r1 = (1.f - fx) * v10 + fx * v11;
        float val = (1.f - fy) * r0 + fy * r1;
        recon[e] = val;
        float d = val - x[e];
        s += (double)d * (double)d;
    }
    double bs = blockReduceSum(s);
    if (threadIdx.x == 0) atomicAdd(&acc[1], bs);
}

__global__ void finalize_kernel(const double* __restrict__ acc, float* __restrict__ out3)
{
    float rec = (float)(acc[1] / 67108864.0);
    float m   = (float)(acc[0] / 8388608.0);
    float vq  = m + 0.25f * m;
    out3[0] = rec + vq;   // loss
    out3[1] = rec;        // recon_loss
    out3[2] = vq;         // vq_loss
}

// ---------------- launch ----------------
extern "C" void kernel_launch(void* const* d_in, const int* in_sizes, int n_in,
                              void* d_out, int out_size)
{
    (void)in_sizes; (void)n_in; (void)out_size;
    const float* x      = (const float*)d_in[0];
    const float* w_spec = (const float*)d_in[1];
    const float* b_spec = (const float*)d_in[2];
    const float* w_e1   = (const float*)d_in[3];
    const float* b_e1   = (const float*)d_in[4];
    const float* w_e2   = (const float*)d_in[5];
    const float* b_e2   = (const float*)d_in[6];
    const float* w_proj = (const float*)d_in[7];
    const float* b_proj = (const float*)d_in[8];
    const float* cb     = (const float*)d_in[9];
    const float* w_rec  = (const float*)d_in[10];
    const float* b_rec  = (const float*)d_in[11];
    const float* w_fin  = (const float*)d_in[12];
    const float* b_fin  = (const float*)d_in[13];

    float* out       = (float*)d_out;
    float* out_recon = out;
    float* out_quant = out + 67108864;
    float* out_idx   = out_quant + 8388608;
    float* out_loss  = out_idx + 65536;

    float *feat2, *feat3, *feat4, *qmap, *rec1, *rs;
    float *we1T, *wcombT, *btab, *we2T, *wprojT, *wrecT, *wfinT, *c2p;
    int* idxp; double* accp;
    cudaGetSymbolAddress((void**)&feat2,  g_feat2);
    cudaGetSymbolAddress((void**)&feat3,  g_feat3);
    cudaGetSymbolAddress((void**)&feat4,  g_feat4);
    cudaGetSymbolAddress((void**)&qmap,   g_qmap);
    cudaGetSymbolAddress((void**)&rec1,   g_rec1);
    cudaGetSymbolAddress((void**)&rs,     g_rs);
    cudaGetSymbolAddress((void**)&we1T,   g_we1T);
    cudaGetSymbolAddress((void**)&wcombT, g_wcombT);
    cudaGetSymbolAddress((void**)&btab,   g_btab);
    cudaGetSymbolAddress((void**)&we2T,   g_we2T);
    cudaGetSymbolAddress((void**)&wprojT, g_wprojT);
    cudaGetSymbolAddress((void**)&wrecT,  g_wrecT);
    cudaGetSymbolAddress((void**)&wfinT,  g_wfinT);
    cudaGetSymbolAddress((void**)&c2p,    g_c2);
    cudaGetSymbolAddress((void**)&idxp,   g_idx);
    cudaGetSymbolAddress((void**)&accp,   g_acc);

    zero_acc_kernel<<<1, 1>>>(accp);
    transpose_kernel<<<(147456 + 255) / 256, 256>>>(w_e1, we1T, 128, 1152);
    fold_w_kernel<<<(73728 + 255) / 256, 256>>>(we1T, w_spec, wcombT);
    fold_b_kernel<<<128, 128>>>(w_e1, b_spec, b_e1, btab);
    transpose_kernel<<<(294912 + 255) / 256, 256>>>(w_e2, we2T, 256, 1152);
    transpose_kernel<<<(32768 + 255) / 256, 256>>>(w_proj, wprojT, 128, 256);
    transpose_kernel<<<(147456 + 255) / 256, 256>>>(w_rec, wrecT, 128, 1152);
    transpose_kernel<<<(8192 + 255) / 256, 256>>>(w_fin, wfinT, 64, 128);
    c2_kernel<<<4, 256>>>(cb, c2p);

    // folded spec+e1 3x3 s2 relu: x[16,64,256,256] -> feat2[16,128,128,128]
    conv3x3_kernel<2, true><<<dim3(2, 128, 16), 256>>>(x, wcombT, btab, feat2, 64, 128, 256, 256, 128, 128, 1);
    // e2 3x3 s2 relu: feat2 -> feat3[16,256,64,64]
    conv3x3_kernel<2, false><<<dim3(1, 64, 32), 256>>>(feat2, we2T, b_e2, feat3, 128, 256, 128, 128, 64, 64, 2);
    // proj 1x1: feat3 -> feat4[16,128,64,64]
    conv1x1_kernel<<<dim3(64, 1, 32), 256>>>(feat3, wprojT, b_proj, feat4, 256, 128, 4096, 2);
    // VQ (fused: argmin + quant tokens + quant NCHW map + vq loss)
    vq_kernel<<<2048, 256>>>(feat4, cb, c2p, idxp, out_idx, qmap, out_quant, accp);
    // rec 3x3 s1 relu: qmap -> rec1
    conv3x3_kernel<1, false><<<dim3(1, 64, 16), 256>>>(qmap, wrecT, b_rec, rec1, 128, 128, 64, 64, 64, 64, 1);
    // fin 1x1 folded BEFORE resize (1x1 conv commutes with bilinear resize): rec1 -> rs[16,64,64,64]
    conv1x1_kernel<<<dim3(64, 1, 16), 256>>>(rec1, wfinT, b_fin, rs, 128, 64, 4096, 1);
    // bilinear x4 upsample + recon write + recon_loss
    resize_loss_kernel<<<4096, 256>>>(rs, x, out_recon, accp);
    finalize_kernel<<<1, 1>>>(accp, out_loss);
}

// round 14
// speedup vs baseline: 1.6067x; 1.0486x over previous
#include <cuda_runtime.h>

// ---------------- scratch buffers (device globals; no allocation allowed) ----------------
static __device__ float g_feat2[33554432];  // [16,128,128,128]
static __device__ float g_feat3[16777216];  // [16,256,64,64]
static __device__ float g_feat4[8388608];   // [16,128,64,64]  (tokens, NCHW)
static __device__ float g_qmap[8388608];    // [16,128,64,64]  quantized NCHW
static __device__ float g_rec1[8388608];    // [16,128,64,64]  relu(conv_rec)
static __device__ float g_rs[4194304];      // [16,64,64,64]   conv_fin(rec1) pre-resize
static __device__ float g_we1T[147456];     // transposed w_e1 (for fold)
static __device__ float g_wcombT[73728];    // folded spec+e1 weights [(ci*9+k)*128+co], ci<64
static __device__ float g_btab[512];        // folded bias table [4][128]
static __device__ float g_we2T[294912];
static __device__ float g_wprojT[32768];
static __device__ float g_wrecT[147456];
static __device__ float g_wfinT[8192];
static __device__ float g_cbT[131072];      // codebook transposed [128][1024]
static __device__ float g_c2[1024];
static __device__ int   g_idx[65536];
static __device__ double g_acc[2];          // [0]=vq sum, [1]=recon sum

typedef unsigned long long u64;

// ---------------- packed f32x2 helpers (sm_103a; ptxas never emits FFMA2 from C++) ----------------
__device__ __forceinline__ u64 pack2(float lo, float hi) {
    u64 r; asm("mov.b64 %0, {%1, %2};" : "=l"(r) : "f"(lo), "f"(hi)); return r;
}
__device__ __forceinline__ float2 unpack2(u64 v) {
    float lo, hi; asm("mov.b64 {%0, %1}, %2;" : "=f"(lo), "=f"(hi) : "l"(v));
    return make_float2(lo, hi);
}
__device__ __forceinline__ void ffma2(u64& d, u64 a, u64 b) {
    asm("fma.rn.f32x2 %0, %1, %2, %0;" : "+l"(d) : "l"(a), "l"(b));
}

// ---------------- helpers ----------------
__device__ __forceinline__ double blockReduceSum(double v) {
    __shared__ double sh[8];
    int lane = threadIdx.x & 31, w = threadIdx.x >> 5;
    #pragma unroll
    for (int o = 16; o; o >>= 1) v += __shfl_down_sync(0xffffffffu, v, o);
    if (lane == 0) sh[w] = v;
    __syncthreads();
    if (w == 0) {
        v = (lane < 8) ? sh[lane] : 0.0;
        #pragma unroll
        for (int o = 4; o; o >>= 1) v += __shfl_down_sync(0xffu, v, o);
    }
    return v;  // valid in thread 0
}

__global__ void zero_acc_kernel(double* acc) { acc[0] = 0.0; acc[1] = 0.0; }

// ---------------- fused prep: all weight transposes + cbT + c2 ----------------
__global__ void prep_kernel(const float* __restrict__ w_e1, const float* __restrict__ w_e2,
                            const float* __restrict__ w_proj, const float* __restrict__ w_rec,
                            const float* __restrict__ w_fin, const float* __restrict__ cb,
                            float* __restrict__ we1T, float* __restrict__ we2T,
                            float* __restrict__ wprojT, float* __restrict__ wrecT,
                            float* __restrict__ wfinT, float* __restrict__ cbT,
                            float* __restrict__ c2)
{
    int e = blockIdx.x * blockDim.x + threadIdx.x;
    if (e < 147456) { int r = e / 1152, c = e % 1152; we1T[c * 128 + r] = w_e1[e]; return; }
    e -= 147456;
    if (e < 294912) { int r = e / 1152, c = e % 1152; we2T[c * 256 + r] = w_e2[e]; return; }
    e -= 294912;
    if (e < 32768)  { int r = e / 256, c = e % 256;   wprojT[c * 128 + r] = w_proj[e]; return; }
    e -= 32768;
    if (e < 147456) { int r = e / 1152, c = e % 1152; wrecT[c * 128 + r] = w_rec[e]; return; }
    e -= 147456;
    if (e < 8192)   { int r = e / 128, c = e % 128;   wfinT[c * 64 + r] = w_fin[e]; return; }
    e -= 8192;
    if (e < 131072) { int d = e >> 10, k = e & 1023;  cbT[e] = cb[k * 128 + d]; return; }
    e -= 131072;
    if (e < 1024) {
        float s = 0.f;
        #pragma unroll 8
        for (int d = 0; d < 128; d++) { float v = cb[e * 128 + d]; s += v * v; }
        c2[e] = s;
    }
}

// fold spec (1x1, 64->128) into e1 (3x3): wcombT[(ci*9+k)*128+co] = sum_c we1T[(c*9+k)*128+co]*wspec[c*64+ci]
__global__ void fold_w_kernel(const float* __restrict__ we1T, const float* __restrict__ wspec,
                              float* __restrict__ wcombT) {
    int e = blockIdx.x * blockDim.x + threadIdx.x;
    if (e >= 64 * 9 * 128) return;
    int co = e & 127; int r = e >> 7; int k = r % 9; int ci = r / 9;
    float s = 0.f;
    #pragma unroll 4
    for (int c = 0; c < 128; c++)
        s += we1T[(c * 9 + k) * 128 + co] * wspec[c * 64 + ci];
    wcombT[(ci * 9 + k) * 128 + co] = s;
}

// border-exact folded bias: btab[t][co], t = (oh==0?0:2)+(ow==0?0:1)
// parallel: one block per co, threads over c, tree-reduce
__global__ void fold_b_kernel(const float* __restrict__ we1, const float* __restrict__ bspec,
                              const float* __restrict__ be1, float* __restrict__ btab) {
    __shared__ float red[4][128];
    int co = blockIdx.x, c = threadIdx.x;
    float bs = bspec[c];
    float w[9];
    #pragma unroll
    for (int k = 0; k < 9; k++) w[k] = we1[co * 1152 + c * 9 + k] * bs;
    float sf = 0.f;
    #pragma unroll
    for (int k = 0; k < 9; k++) sf += w[k];
    red[0][c] = sf;
    red[1][c] = w[0] + w[1] + w[2];   // ky==0 row (missing when oh==0)
    red[2][c] = w[0] + w[3] + w[6];   // kx==0 col (missing when ow==0)
    red[3][c] = w[0];
    __syncthreads();
    for (int o = 64; o; o >>= 1) {
        if (c < o) {
            #pragma unroll
            for (int q = 0; q < 4; q++) red[q][c] += red[q][c + o];
        }
        __syncthreads();
    }
    if (c == 0) {
        float base = be1[co];
        float tf = red[0][0], tr = red[1][0], tc = red[2][0], t00 = red[3][0];
        btab[0 * 128 + co] = base + tf - tr - tc + t00;
        btab[1 * 128 + co] = base + tf - tr;
        btab[2 * 128 + co] = base + tf - tc;
        btab[3 * 128 + co] = base + tf;
    }
}

// ---------------- 1x1 conv: block = 64 px x 64 co, thread = 4 px x 4 consecutive co ----------------
// packed f32x2 over the co dimension: weight pairs come straight from LDS.128
__global__ __launch_bounds__(256)
void conv1x1_kernel(const float* __restrict__ in, const float* __restrict__ wT,
                    const float* __restrict__ bias, float* __restrict__ out,
                    int Cin, int Cout, int P, int nCoT)
{
    __shared__ __align__(16) float in_s[32][64];
    __shared__ __align__(16) float w_s[32][64];
    int b   = blockIdx.z / nCoT;
    int co0 = (blockIdx.z % nCoT) * 64;
    int p0  = blockIdx.x * 64;
    int tid = threadIdx.x;
    int pl = tid & 15, cg = tid >> 4;   // pl: pixel group (4 px), cg: 4 consecutive co

    u64 accp[2][4];                      // [co pair][pixel]
    #pragma unroll
    for (int p = 0; p < 2; p++)
        #pragma unroll
        for (int j = 0; j < 4; j++) accp[p][j] = 0ULL;

    const float* inb = in + (size_t)b * Cin * P + p0;

    for (int ci0 = 0; ci0 < Cin; ci0 += 32) {
        __syncthreads();
        #pragma unroll
        for (int e = tid; e < 2048; e += 256) {
            int ci = e >> 6, p = e & 63;
            in_s[ci][p] = inb[(size_t)(ci0 + ci) * P + p];
        }
        for (int e = tid; e < 2048; e += 256) {
            int ci = e >> 6, c = e & 63;
            w_s[ci][c] = wT[(size_t)(ci0 + ci) * Cout + co0 + c];
        }
        __syncthreads();
        #pragma unroll 4
        for (int ci = 0; ci < 32; ci++) {
            float4 iv = *(const float4*)&in_s[ci][pl * 4];
            u64 ivb[4] = {pack2(iv.x, iv.x), pack2(iv.y, iv.y),
                          pack2(iv.z, iv.z), pack2(iv.w, iv.w)};
            ulonglong2 w2 = *(const ulonglong2*)&w_s[ci][cg * 4];
            #pragma unroll
            for (int j = 0; j < 4; j++) { ffma2(accp[0][j], w2.x, ivb[j]); }
            #pragma unroll
            for (int j = 0; j < 4; j++) { ffma2(accp[1][j], w2.y, ivb[j]); }
        }
    }
    #pragma unroll
    for (int p = 0; p < 2; p++) {
        int coA = co0 + cg * 4 + p * 2;
        float bA = bias[coA], bB = bias[coA + 1];
        float2 v0 = unpack2(accp[p][0]), v1 = unpack2(accp[p][1]);
        float2 v2 = unpack2(accp[p][2]), v3 = unpack2(accp[p][3]);
        float4 oA, oB;
        oA.x = v0.x + bA; oA.y = v1.x + bA; oA.z = v2.x + bA; oA.w = v3.x + bA;
        oB.x = v0.y + bB; oB.y = v1.y + bB; oB.z = v2.y + bB; oB.w = v3.y + bB;
        *(float4*)&out[((size_t)b * Cout + coA)     * P + p0 + pl * 4] = oA;
        *(float4*)&out[((size_t)b * Cout + coA + 1) * P + p0 + pl * 4] = oB;
    }
}

// ---------------- 3x3 conv (stride templated), relu; block = 64 px row x 128 co ----------------
// thread = 4 px x 8 consecutive co; f32x2 packed over co (4 co-pairs), weight pairs direct from LDS.128
// BTAB: bias is a [4][Cout] table selected by (oh==0, ow==0) -- used by the folded spec+e1 conv
template<int STRIDE, bool BTAB>
__global__ __launch_bounds__(256)
void conv3x3_kernel(const float* __restrict__ in, const float* __restrict__ wT,
                    const float* __restrict__ bias, float* __restrict__ out,
                    int Cin, int Cout, int IH, int IW, int OH, int OW, int nCoT)
{
    const int SW = 64 * STRIDE + 4;
    const int NV = 3 * STRIDE + 3;
    __shared__ __align__(16) float in_s[4][3][64 * STRIDE + 4];
    __shared__ __align__(16) float w_s[4][9][128];

    int b   = blockIdx.z / nCoT;
    int co0 = (blockIdx.z % nCoT) * 128;
    int oh  = blockIdx.y;
    int ow0 = blockIdx.x * 64;
    int tid = threadIdx.x;
    int pl = tid & 15, cg = tid >> 4;

    u64 accp[4][4];                      // [co pair][pixel]
    #pragma unroll
    for (int q = 0; q < 4; q++)
        #pragma unroll
        for (int j = 0; j < 4; j++) accp[q][j] = 0ULL;

    const float* inb = in + (size_t)b * Cin * IH * IW;
    const int xlim = 63 * STRIDE + 2;

    for (int ci0 = 0; ci0 < Cin; ci0 += 4) {
        __syncthreads();
        int tot = 4 * 3 * SW;
        for (int e = tid; e < tot; e += 256) {
            int ci = e / (3 * SW); int r = e % (3 * SW);
            int ky = r / SW; int xx = r % SW;
            int iy = oh * STRIDE + ky - 1;
            int ix = ow0 * STRIDE + xx - 1;
            float v = 0.f;
            if ((unsigned)iy < (unsigned)IH && (unsigned)ix < (unsigned)IW && xx <= xlim)
                v = inb[((size_t)(ci0 + ci) * IH + iy) * IW + ix];
            in_s[ci][ky][xx] = v;
        }
        for (int e = tid; e < 4608; e += 256) {
            int ci = e / 1152; int r = e % 1152;
            int k = r >> 7; int c = r & 127;
            w_s[ci][k][c] = wT[((size_t)(ci0 + ci) * 9 + k) * Cout + co0 + c];
        }
        __syncthreads();
        for (int ci = 0; ci < 4; ci++) {
            #pragma unroll
            for (int ky = 0; ky < 3; ky++) {
                float iv[NV];
                if (STRIDE == 2) {
                    float4 a  = *(const float4*)&in_s[ci][ky][pl * 8];
                    float4 b4 = *(const float4*)&in_s[ci][ky][pl * 8 + 4];
                    iv[0] = a.x;  iv[1] = a.y;  iv[2] = a.z;  iv[3] = a.w;
                    iv[4] = b4.x; iv[5] = b4.y; iv[6] = b4.z; iv[7] = b4.w;
                    iv[8] = in_s[ci][ky][pl * 8 + 8];
                } else {
                    float4 a = *(const float4*)&in_s[ci][ky][pl * 4];
                    iv[0] = a.x; iv[1] = a.y; iv[2] = a.z; iv[3] = a.w;
                    iv[4] = in_s[ci][ky][pl * 4 + 4];
                    iv[5] = in_s[ci][ky][pl * 4 + 5];
                }
                u64 ivb[NV];
                #pragma unroll
                for (int v = 0; v < NV; v++) ivb[v] = pack2(iv[v], iv[v]);
                #pragma unroll
                for (int kx = 0; kx < 3; kx++) {
                    const ulonglong2* wrow = (const ulonglong2*)&w_s[ci][ky * 3 + kx][cg * 8];
                    ulonglong2 wA = wrow[0], wB = wrow[1];
                    u64 wq[4] = {wA.x, wA.y, wB.x, wB.y};
                    #pragma unroll
                    for (int q = 0; q < 4; q++)
                        #pragma unroll
                        for (int j = 0; j < 4; j++)
                            ffma2(accp[q][j], wq[q], ivb[j * STRIDE + kx]);
                }
            }
        }
    }
    #pragma unroll
    for (int q = 0; q < 4; q++) {
        int coA = co0 + cg * 8 + q * 2;
        int coB = coA + 1;
        float2 v0 = unpack2(accp[q][0]), v1 = unpack2(accp[q][1]);
        float2 v2 = unpack2(accp[q][2]), v3 = unpack2(accp[q][3]);
        float4 oA, oB;
        if (BTAB) {
            int rbase = (oh == 0) ? 0 : 2;
            float pa[4] = {v0.x, v1.x, v2.x, v3.x};
            float pb[4] = {v0.y, v1.y, v2.y, v3.y};
            float ra[4], rb[4];
            #pragma unroll
            for (int j = 0; j < 4; j++) {
                int ow = ow0 + pl * 4 + j;
                int t = rbase + (ow == 0 ? 0 : 1);
                ra[j] = fmaxf(pa[j] + bias[t * Cout + coA], 0.f);
                rb[j] = fmaxf(pb[j] + bias[t * Cout + coB], 0.f);
            }
            oA.x = ra[0]; oA.y = ra[1]; oA.z = ra[2]; oA.w = ra[3];
            oB.x = rb[0]; oB.y = rb[1]; oB.z = rb[2]; oB.w = rb[3];
        } else {
            float bA = bias[coA], bB = bias[coB];
            oA.x = fmaxf(v0.x + bA, 0.f); oA.y = fmaxf(v1.x + bA, 0.f);
            oA.z = fmaxf(v2.x + bA, 0.f); oA.w = fmaxf(v3.x + bA, 0.f);
            oB.x = fmaxf(v0.y + bB, 0.f); oB.y = fmaxf(v1.y + bB, 0.f);
            oB.z = fmaxf(v2.y + bB, 0.f); oB.w = fmaxf(v3.y + bB, 0.f);
        }
        *(float4*)&out[(((size_t)b * Cout + coA) * OH + oh) * OW + ow0 + pl * 4] = oA;
        *(float4*)&out[(((size_t)b * Cout + coB) * OH + oh) * OW + ow0 + pl * 4] = oB;
    }
}

// ---------------- VQ argmin + fused quantized writes + vq-loss: block = 32 tokens ----------------
// thread = 2 adjacent tokens x 4 adjacent codes; codebook pre-transposed (cbT) so smem fill is
// coalesced + conflict-free; inner loop: 3 LDS(float2) + 8 FMA per d (was 4 LDS + 4 FMA).
// Distances bit-identical to previous version (same d-order accumulation, same expression).
__global__ __launch_bounds__(256)
void vq_kernel(const float* __restrict__ feat, const float* __restrict__ cb,
               const float* __restrict__ cbT, const float* __restrict__ c2,
               int* __restrict__ idx_out, float* __restrict__ idxf_out,
               float* __restrict__ qmap, float* __restrict__ qout, double* __restrict__ acc)
{
    __shared__ __align__(8) float z_s[128][32];
    __shared__ __align__(8) float c_sT[128][66];   // pad 2: row stride 264B (8B-aligned), no STS conflicts
    __shared__ float z2_s[32];
    __shared__ float redv[32][16];
    __shared__ int   redi[32][16];
    __shared__ int   bsel[32];

    int nb = blockIdx.x;
    int b = nb >> 7; int p0 = (nb & 127) << 5;
    int tid = threadIdx.x;

    for (int e = tid; e < 4096; e += 256) {
        int d = e >> 5, t = e & 31;
        z_s[d][t] = feat[((size_t)b * 128 + d) * 4096 + p0 + t];
    }
    __syncthreads();
    if (tid < 32) {
        float s = 0.f;
        #pragma unroll 8
        for (int d = 0; d < 128; d++) { float v = z_s[d][tid]; s += v * v; }
        z2_s[tid] = s;
    }
    __syncthreads();

    int tp = tid & 15, cg = tid >> 4;   // tokens {2tp, 2tp+1}, codes {k0 + 4cg .. +3}
    const float INF = __int_as_float(0x7f800000);
    float best0 = INF, best1 = INF;
    int bi0 = 0, bi1 = 0;
    float z20 = z2_s[tp * 2], z21 = z2_s[tp * 2 + 1];

    for (int k0 = 0; k0 < 1024; k0 += 64) {
        __syncthreads();
        for (int e = tid; e < 8192; e += 256) {
            int kk = e & 63, d = e >> 6;
            c_sT[d][kk] = cbT[(size_t)d * 1024 + k0 + kk];
        }
        __syncthreads();
        float dt0[4] = {0.f, 0.f, 0.f, 0.f};
        float dt1[4] = {0.f, 0.f, 0.f, 0.f};
        #pragma unroll 4
        for (int d = 0; d < 128; d++) {
            float2 z  = *(const float2*)&z_s[d][tp * 2];
            float2 ca = *(const float2*)&c_sT[d][cg * 4];
            float2 cc = *(const float2*)&c_sT[d][cg * 4 + 2];
            dt0[0] += z.x * ca.x; dt0[1] += z.x * ca.y; dt0[2] += z.x * cc.x; dt0[3] += z.x * cc.y;
            dt1[0] += z.y * ca.x; dt1[1] += z.y * ca.y; dt1[2] += z.y * cc.x; dt1[3] += z.y * cc.y;
        }
        #pragma unroll
        for (int j = 0; j < 4; j++) {
            int k = k0 + cg * 4 + j;
            float cc2 = __ldg(&c2[k]);
            float v0 = (z20 - 2.f * dt0[j]) + cc2;
            float v1 = (z21 - 2.f * dt1[j]) + cc2;
            if (v0 < best0) { best0 = v0; bi0 = k; }
            if (v1 < best1) { best1 = v1; bi1 = k; }
        }
    }
    redv[tp * 2][cg] = best0;     redi[tp * 2][cg] = bi0;
    redv[tp * 2 + 1][cg] = best1; redi[tp * 2 + 1][cg] = bi1;
    __syncthreads();
    if (tid < 32) {
        float bv = redv[tid][0]; int bi = redi[tid][0];
        for (int g = 1; g < 16; g++) {
            float v = redv[tid][g]; int i = redi[tid][g];
            if (v < bv || (v == bv && i < bi)) { bv = v; bi = i; }
        }
        int n = b * 4096 + p0 + tid;
        idx_out[n] = bi;
        idxf_out[n] = (float)bi;
        bsel[tid] = bi;
    }
    __syncthreads();

    // fused epilogue: quantized tokens [N,128] (c-fast, coalesced)
    for (int e = tid; e < 4096; e += 256) {
        int c = e & 127, t = e >> 7;
        qout[((size_t)(b * 4096 + p0 + t)) * 128 + c] = __ldg(&cb[bsel[t] * 128 + c]);
    }
    // fused epilogue: quantized NCHW map (t-fast, coalesced) + vq-loss sum
    double vs = 0.0;
    for (int e = tid; e < 4096; e += 256) {
        int t = e & 31, c = e >> 5;
        float q = __ldg(&cb[bsel[t] * 128 + c]);
        float z = z_s[c][t];
        qmap[((size_t)b * 128 + c) * 4096 + p0 + t] = q;
        float d = q - z;
        vs += (double)d * (double)d;
    }
    double bs2 = blockReduceSum(vs);
    if (tid == 0) atomicAdd(&acc[0], bs2);
}

// ---------------- bilinear x4 upsample (64->256) + recon write + recon-loss ----------------
__global__ __launch_bounds__(256)
void resize_loss_kernel(const float* __restrict__ rs, const float* __restrict__ x,
                        float* __restrict__ recon, double* __restrict__ acc)
{
    const size_t total = 67108864;
    size_t stride = (size_t)gridDim.x * blockDim.x;
    double s = 0.0;
    for (size_t e = (size_t)blockIdx.x * blockDim.x + threadIdx.x; e < total; e += stride) {
        int xq = (int)(e & 255);
        int yq = (int)((e >> 8) & 255);
        int c  = (int)((e >> 16) & 63);
        int b  = (int)(e >> 22);
        int ry = yq & 3, ky = yq >> 2;
        int rx = xq & 3, kx = xq >> 2;
        float fy = (ry == 0) ? 0.625f : (ry == 1) ? 0.875f : (ry == 2) ? 0.125f : 0.375f;
        float fx = (rx == 0) ? 0.625f : (rx == 1) ? 0.875f : (rx == 2) ? 0.125f : 0.375f;
        int y0 = ky + ((ry < 2) ? -1 : 0);
        int x0 = kx + ((rx < 2) ? -1 : 0);
        int y1 = min(y0 + 1, 63); y0 = max(y0, 0);
        int x1 = min(x0 + 1, 63); x0 = max(x0, 0);
        const float* base = rs + (((size_t)b * 64 + c) << 12);
        float v00 = base[y0 * 64 + x0], v01 = base[y0 * 64 + x1];
        float v10 = base[y1 * 64 + x0], v11 = base[y1 * 64 + x1];
        float r0 = (1.f - fx) * v00 + fx * v01;
        float r1 = (1.f - fx) * v10 + fx * v11;
        float val = (1.f - fy) * r0 + fy * r1;
        recon[e] = val;
        float d = val - x[e];
        s += (double)d * (double)d;
    }
    double bs = blockReduceSum(s);
    if (threadIdx.x == 0) atomicAdd(&acc[1], bs);
}

__global__ void finalize_kernel(const double* __restrict__ acc, float* __restrict__ out3)
{
    float rec = (float)(acc[1] / 67108864.0);
    float m   = (float)(acc[0] / 8388608.0);
    float vq  = m + 0.25f * m;
    out3[0] = rec + vq;   // loss
    out3[1] = rec;        // recon_loss
    out3[2] = vq;         // vq_loss
}

// ---------------- launch ----------------
extern "C" void kernel_launch(void* const* d_in, const int* in_sizes, int n_in,
                              void* d_out, int out_size)
{
    (void)in_sizes; (void)n_in; (void)out_size;
    const float* x      = (const float*)d_in[0];
    const float* w_spec = (const float*)d_in[1];
    const float* b_spec = (const float*)d_in[2];
    const float* w_e1   = (const float*)d_in[3];
    const float* b_e1   = (const float*)d_in[4];
    const float* w_e2   = (const float*)d_in[5];
    const float* b_e2   = (const float*)d_in[6];
    const float* w_proj = (const float*)d_in[7];
    const float* b_proj = (const float*)d_in[8];
    const float* cb     = (const float*)d_in[9];
    const float* w_rec  = (const float*)d_in[10];
    const float* b_rec  = (const float*)d_in[11];
    const float* w_fin  = (const float*)d_in[12];
    const float* b_fin  = (const float*)d_in[13];

    float* out       = (float*)d_out;
    float* out_recon = out;
    float* out_quant = out + 67108864;
    float* out_idx   = out_quant + 8388608;
    float* out_loss  = out_idx + 65536;

    float *feat2, *feat3, *feat4, *qmap, *rec1, *rs;
    float *we1T, *wcombT, *btab, *we2T, *wprojT, *wrecT, *wfinT, *cbT, *c2p;
    int* idxp; double* accp;
    cudaGetSymbolAddress((void**)&feat2,  g_feat2);
    cudaGetSymbolAddress((void**)&feat3,  g_feat3);
    cudaGetSymbolAddress((void**)&feat4,  g_feat4);
    cudaGetSymbolAddress((void**)&qmap,   g_qmap);
    cudaGetSymbolAddress((void**)&rec1,   g_rec1);
    cudaGetSymbolAddress((void**)&rs,     g_rs);
    cudaGetSymbolAddress((void**)&we1T,   g_we1T);
    cudaGetSymbolAddress((void**)&wcombT, g_wcombT);
    cudaGetSymbolAddress((void**)&btab,   g_btab);
    cudaGetSymbolAddress((void**)&we2T,   g_we2T);
    cudaGetSymbolAddress((void**)&wprojT, g_wprojT);
    cudaGetSymbolAddress((void**)&wrecT,  g_wrecT);
    cudaGetSymbolAddress((void**)&wfinT,  g_wfinT);
    cudaGetSymbolAddress((void**)&cbT,    g_cbT);
    cudaGetSymbolAddress((void**)&c2p,    g_c2);
    cudaGetSymbolAddress((void**)&idxp,   g_idx);
    cudaGetSymbolAddress((void**)&accp,   g_acc);

    // launch #0: fused prep (all transposes + cbT + c2); 763904 total elements
    prep_kernel<<<(763904 + 255) / 256, 256>>>(w_e1, w_e2, w_proj, w_rec, w_fin, cb,
                                               we1T, we2T, wprojT, wrecT, wfinT, cbT, c2p);
    // #1, #2, #3
    fold_w_kernel<<<(73728 + 255) / 256, 256>>>(we1T, w_spec, wcombT);
    fold_b_kernel<<<128, 128>>>(w_e1, b_spec, b_e1, btab);
    zero_acc_kernel<<<1, 1>>>(accp);

    // #4: folded spec+e1 3x3 s2 relu: x[16,64,256,256] -> feat2[16,128,128,128]
    conv3x3_kernel<2, true><<<dim3(2, 128, 16), 256>>>(x, wcombT, btab, feat2, 64, 128, 256, 256, 128, 128, 1);
    // #5 (ncu -s 5 captures this): e2 3x3 s2 relu: feat2 -> feat3[16,256,64,64]
    conv3x3_kernel<2, false><<<dim3(1, 64, 32), 256>>>(feat2, we2T, b_e2, feat3, 128, 256, 128, 128, 64, 64, 2);
    // proj 1x1: feat3 -> feat4[16,128,64,64]
    conv1x1_kernel<<<dim3(64, 1, 32), 256>>>(feat3, wprojT, b_proj, feat4, 256, 128, 4096, 2);
    // VQ (fused: argmin + quant tokens + quant NCHW map + vq loss)
    vq_kernel<<<2048, 256>>>(feat4, cb, cbT, c2p, idxp, out_idx, qmap, out_quant, accp);
    // rec 3x3 s1 relu: qmap -> rec1
    conv3x3_kernel<1, false><<<dim3(1, 64, 16), 256>>>(qmap, wrecT, b_rec, rec1, 128, 128, 64, 64, 64, 64, 1);
    // fin 1x1 folded BEFORE resize (1x1 conv commutes with bilinear resize): rec1 -> rs[16,64,64,64]
    conv1x1_kernel<<<dim3(64, 1, 16), 256>>>(rec1, wfinT, b_fin, rs, 128, 64, 4096, 1);
    // bilinear x4 upsample + recon write + recon_loss
    resize_loss_kernel<<<4096, 256>>>(rs, x, out_recon, accp);
    finalize_kernel<<<1, 1>>>(accp, out_loss);
}